// round 6
// baseline (speedup 1.0000x reference)
#include <cuda_runtime.h>
#include <math.h>

// ---------------- sizes ----------------
#define BATCH 16
#define H0 256
#define W0 256
#define CIN 3
#define HID 128
#define EMB 64
#define KCODES 1024
#define H1v 128
#define W1v 128
#define H2v 64
#define W2v 64

#define XREC_ELEMS (BATCH*H0*W0*3)      // 3145728
#define TOK_OFF    XREC_ELEMS
#define TOK_ELEMS  (BATCH*H2v*W2v)      // 65536
#define LOSS_OFF   (TOK_OFF + TOK_ELEMS)

typedef unsigned long long u64;

// ---------------- scratch ----------------
__device__ float g_h1[BATCH*H1v*W1v*HID];   // encoder conv1 out (gelu'd)
__device__ float g_ze[BATCH*H2v*W2v*EMB];   // z_e
__device__ float g_zst[BATCH*H2v*W2v*EMB];  // z_st
__device__ float g_g1[BATCH*H1v*W1v*HID];   // decoder convt1 out (gelu'd)
__device__ float g_loss;

__device__ __forceinline__ float gelu_f(float x) {
    float t = 0.7978845608028654f * (x + 0.044715f * x * x * x);
    return 0.5f * x * (1.0f + tanhf(t));
}

// ---------------- packed f32x2 helpers ----------------
__device__ __forceinline__ u64 splat2(float a) {
    u64 r; asm("mov.b64 %0, {%1, %1};" : "=l"(r) : "f"(a)); return r;
}
__device__ __forceinline__ u64 pack2(float lo, float hi) {
    u64 r; asm("mov.b64 %0, {%1, %2};" : "=l"(r) : "f"(lo), "f"(hi)); return r;
}
__device__ __forceinline__ void unpack2(u64 v, float& lo, float& hi) {
    asm("mov.b64 {%0, %1}, %2;" : "=f"(lo), "=f"(hi) : "l"(v));
}
__device__ __forceinline__ void ffma2(u64& d, u64 a, u64 b) {
    asm("fma.rn.f32x2 %0, %1, %2, %0;" : "+l"(d) : "l"(a), "l"(b));
}

// FFMA2 over 8 co (4 packed pairs) for one a-scalar
#define FFMA2_8(J, AJ) { u64 s_ = splat2(AJ); \
    ffma2(acc2[J][0], s_, w01); ffma2(acc2[J][1], s_, w23); \
    ffma2(acc2[J][2], s_, w45); ffma2(acc2[J][3], s_, w67); }

// ---------------- cp.async helpers ----------------
__device__ __forceinline__ void cp16(float* smem_dst, const float* gsrc) {
    unsigned sa = (unsigned)__cvta_generic_to_shared(smem_dst);
    asm volatile("cp.async.cg.shared.global [%0], [%1], 16;" :: "r"(sa), "l"(gsrc));
}
#define CP_COMMIT() asm volatile("cp.async.commit_group;")
#define CP_WAIT0()  asm volatile("cp.async.wait_group 0;")

// ================= conv1: x[16,256,256,3] -> h1[16,128,128,128], 4x4 s2 SAME, gelu =================
__global__ void k_conv1(const float* __restrict__ x, const float* __restrict__ w,
                        const float* __restrict__ b) {
    __shared__ float ws[4*4*3*128];   // 24 KB
    __shared__ float ins[4*34*3];     // input tile
    int tid = threadIdx.x;
    int bx = blockIdx.x, oy = blockIdx.y, n = blockIdx.z;
    if (bx == 0 && oy == 0 && n == 0 && tid == 0) g_loss = 0.0f;
    for (int i = tid; i < 6144; i += 128) ws[i] = w[i];
    int x0 = bx * 16;
    for (int i = tid; i < 4*34*3; i += 128) {
        int r = i / (34*3); int rem = i - r*(34*3); int c = rem / 3; int ch = rem % 3;
        int gy = 2*oy - 1 + r;
        int gx = 2*x0 - 1 + c;
        float v = 0.0f;
        if (gy >= 0 && gy < H0 && gx >= 0 && gx < W0) v = x[((n*H0+gy)*W0+gx)*CIN + ch];
        ins[i] = v;
    }
    __syncthreads();
    int co = tid;
    float bias = b[co];
    u64 acc2[8];
#pragma unroll
    for (int pp = 0; pp < 8; pp++) acc2[pp] = pack2(bias, bias);
    for (int ky = 0; ky < 4; ky++) {
        for (int kx = 0; kx < 4; kx++) {
#pragma unroll
            for (int ci = 0; ci < 3; ci++) {
                float wv = ws[((ky*4+kx)*3+ci)*128 + co];
                u64 wvv = splat2(wv);
#pragma unroll
                for (int pp = 0; pp < 8; pp++) {
                    u64 av = pack2(ins[(ky*34 + 4*pp + kx)*3 + ci],
                                   ins[(ky*34 + 4*pp + 2 + kx)*3 + ci]);
                    ffma2(acc2[pp], av, wvv);
                }
            }
        }
    }
#pragma unroll
    for (int pp = 0; pp < 8; pp++) {
        float v0, v1; unpack2(acc2[pp], v0, v1);
        g_h1[((n*H1v+oy)*W1v + x0 + 2*pp)*HID + co]     = gelu_f(v0);
        g_h1[((n*H1v+oy)*W1v + x0 + 2*pp + 1)*HID + co] = gelu_f(v1);
    }
}

// ================= conv2 (pipelined GEMM, f32x2) + gelu + 1x1(128->64): h1 -> z_e =================
// block = 128 threads. tile: 64 ox (one row) x 128 co. grid (64 oy, 16 n). dyn smem.
// smem: ins [4r*4cik][132] = 2112 | Bs double buf 2 x 8192
__global__ void __launch_bounds__(128) k_conv2(const float* __restrict__ w2, const float* __restrict__ b2,
                                               const float* __restrict__ w3, const float* __restrict__ b3) {
    extern __shared__ float sm[];
    float* ins = sm;                        // 2112
    float* h2s = sm;                        // reused after main loop: [64 px][132]
    int tid = threadIdx.x;
    int oy = blockIdx.x, n = blockIdx.y;
    int pa = tid & 7, cg = tid >> 3;        // pa: px group, cg: co group (0..15)
    int co0 = cg * 8;
    u64 acc2[8][4];
    {
        float4 b0 = *reinterpret_cast<const float4*>(&b2[co0]);
        float4 b1 = *reinterpret_cast<const float4*>(&b2[co0+4]);
        u64 p0 = pack2(b0.x,b0.y), p1 = pack2(b0.z,b0.w);
        u64 p2 = pack2(b1.x,b1.y), p3 = pack2(b1.z,b1.w);
#pragma unroll
        for (int j = 0; j < 8; j++) { acc2[j][0]=p0; acc2[j][1]=p1; acc2[j][2]=p2; acc2[j][3]=p3; }
    }
    int axbase = 2 * pa;

    float4 pin[5];
    // ins LDG (chunk ch) -> regs
    auto ldg_ins = [&](int ch) {
        int ci0 = ch * 4;
#pragma unroll
        for (int u = 0; u < 5; u++) {
            int i = tid + u*128;
            if (i < 520) {
                int r = i / 130; int ixl = i - r*130;
                int iy = 2*oy - 1 + r;
                int ix = ixl - 1;
                float4 v = make_float4(0,0,0,0);
                if (iy >= 0 && iy < H1v && ix >= 0 && ix < W1v)
                    v = *reinterpret_cast<const float4*>(&g_h1[((n*H1v+iy)*W1v+ix)*HID + ci0]);
                pin[u] = v;
            }
        }
    };
    // regs -> ins smem (transposed scatter)
    auto sts_ins = [&]() {
#pragma unroll
        for (int u = 0; u < 5; u++) {
            int i = tid + u*128;
            if (i < 520) {
                int r = i / 130; int ixl = i - r*130;
                float* dst = &ins[(r*4)*132 + ixl];
                float4 v = pin[u];
                dst[0] = v.x; dst[132] = v.y; dst[264] = v.z; dst[396] = v.w;
            }
        }
    };
    // weights chunk -> Bs buffer (cp.async)
    auto cp_bs = [&](int ch, float* Bbuf) {
        int ci0 = ch * 4;
#pragma unroll
        for (int u = 0; u < 16; u++) {
            int i = tid + u*128;    // float4 index in [0, 2048)
            int co4 = i & 31; int cik = (i >> 5) & 3; int tap = i >> 7;
            cp16(&Bbuf[(tap*4+cik)*128 + co4*4],
                 &w2[((tap*HID) + ci0 + cik)*HID + co4*4]);
        }
        CP_COMMIT();
    };

    cp_bs(0, sm + 2112);
    ldg_ins(0);
    sts_ins();
    CP_WAIT0();
    __syncthreads();
#pragma unroll 1
    for (int ch = 0; ch < 32; ch++) {
        float* Bs = sm + 2112 + (ch & 1) * 8192;
        if (ch < 31) {
            cp_bs(ch+1, sm + 2112 + ((ch+1) & 1) * 8192);
            ldg_ins(ch+1);
        }
        for (int tap = 0; tap < 16; tap++) {
            int kx = tap & 3; int row = tap >> 2;
#pragma unroll
            for (int cik = 0; cik < 4; cik++) {
                const u64* bp = reinterpret_cast<const u64*>(&Bs[(tap*4+cik)*128 + co0]);
                u64 w01 = bp[0], w23 = bp[1], w45 = bp[2], w67 = bp[3];
                const float* ap = &ins[(row*4+cik)*132 + axbase + kx];
                float a0 = ap[0],  a1 = ap[16], a2 = ap[32], a3 = ap[48];
                float a4 = ap[64], a5 = ap[80], a6 = ap[96], a7 = ap[112];
                FFMA2_8(0,a0) FFMA2_8(1,a1) FFMA2_8(2,a2) FFMA2_8(3,a3)
                FFMA2_8(4,a4) FFMA2_8(5,a5) FFMA2_8(6,a6) FFMA2_8(7,a7)
            }
        }
        __syncthreads();
        if (ch < 31) {
            sts_ins();
            CP_WAIT0();
        }
        __syncthreads();
    }
    // gelu -> h2s [64 px][132]
#pragma unroll
    for (int j = 0; j < 8; j++) {
        int ox = pa + 8*j;
        float f0,f1,f2,f3,f4,f5,f6,f7;
        unpack2(acc2[j][0], f0, f1); unpack2(acc2[j][1], f2, f3);
        unpack2(acc2[j][2], f4, f5); unpack2(acc2[j][3], f6, f7);
        float4 o0 = make_float4(gelu_f(f0), gelu_f(f1), gelu_f(f2), gelu_f(f3));
        float4 o1 = make_float4(gelu_f(f4), gelu_f(f5), gelu_f(f6), gelu_f(f7));
        *reinterpret_cast<float4*>(&h2s[ox*132 + co0])     = o0;
        *reinterpret_cast<float4*>(&h2s[ox*132 + co0 + 4]) = o1;
    }
    __syncthreads();
    // fused 1x1: 128 -> 64, each thread: one px-half, 32 embeds (f32x2)
    {
        int px = tid >> 1;
        int e0 = (tid & 1) * 32;
        u64 z2[16];
#pragma unroll
        for (int u = 0; u < 8; u++) {
            float4 bb = *reinterpret_cast<const float4*>(&b3[e0 + 4*u]);
            z2[2*u]   = pack2(bb.x, bb.y);
            z2[2*u+1] = pack2(bb.z, bb.w);
        }
#pragma unroll 4
        for (int ci = 0; ci < 128; ci++) {
            float hv = h2s[px*132 + ci];
            u64 s = splat2(hv);
#pragma unroll
            for (int u = 0; u < 8; u++) {
                float4 wv = *reinterpret_cast<const float4*>(&w3[ci*EMB + e0 + 4*u]);
                ffma2(z2[2*u],   s, pack2(wv.x, wv.y));
                ffma2(z2[2*u+1], s, pack2(wv.z, wv.w));
            }
        }
        float* dst = &g_ze[((n*H2v+oy)*W2v + px)*EMB + e0];
#pragma unroll
        for (int u = 0; u < 8; u++) {
            float f0,f1,f2,f3;
            unpack2(z2[2*u], f0, f1); unpack2(z2[2*u+1], f2, f3);
            *reinterpret_cast<float4*>(dst + 4*u) = make_float4(f0, f1, f2, f3);
        }
    }
}

// ================= VQ: argmin over 1024 codes, tok + z_st + loss =================
#define CSTR 68
__global__ void k_vq(const float* __restrict__ cb, float* __restrict__ dout) {
    __shared__ float cs[64*CSTR];
    __shared__ float e2s[64];
    __shared__ float bval[128];
    __shared__ int   bidx[128];
    __shared__ int   widx[16];
    __shared__ float lred[128];
    int tid = threadIdx.x;
    int pb = blockIdx.x * 16;
    int p = tid & 15;
    int g = tid >> 4;   // 0..7
    float4 z4[16];
    const float* zp = &g_ze[(pb + p)*EMB];
#pragma unroll
    for (int i = 0; i < 16; i++) z4[i] = *reinterpret_cast<const float4*>(&zp[4*i]);
    float best = 3.4e38f; int bi = 0;
    for (int ch = 0; ch < 16; ch++) {
        for (int i = tid; i < 64*16; i += 128) {
            int cj = i >> 4; int d4 = i & 15;
            float4 v = *reinterpret_cast<const float4*>(&cb[(ch*64+cj)*EMB + 4*d4]);
            *reinterpret_cast<float4*>(&cs[cj*CSTR + 4*d4]) = v;
        }
        __syncthreads();
        if (tid < 64) {
            float s = 0.0f;
#pragma unroll 8
            for (int d = 0; d < 64; d++) { float c = cs[tid*CSTR + d]; s = fmaf(c, c, s); }
            e2s[tid] = s;
        }
        __syncthreads();
#pragma unroll
        for (int j = 0; j < 8; j++) {
            int cj = g*8 + j;
            const float* cp = &cs[cj*CSTR];
            float dot = 0.0f;
#pragma unroll
            for (int i = 0; i < 16; i++) {
                float4 c = *reinterpret_cast<const float4*>(&cp[4*i]);
                dot = fmaf(z4[i].x, c.x, dot); dot = fmaf(z4[i].y, c.y, dot);
                dot = fmaf(z4[i].z, c.z, dot); dot = fmaf(z4[i].w, c.w, dot);
            }
            float dist = e2s[cj] - 2.0f*dot;
            int gidx = ch*64 + cj;
            if (dist < best || (dist == best && gidx < bi)) { best = dist; bi = gidx; }
        }
        __syncthreads();
    }
    bval[tid] = best; bidx[tid] = bi;
    __syncthreads();
    if (tid < 16) {
        float bb = bval[tid]; int bbi = bidx[tid];
        for (int k = 1; k < 8; k++) {
            float v = bval[tid + 16*k]; int vi = bidx[tid + 16*k];
            if (v < bb || (v == bb && vi < bbi)) { bb = v; bbi = vi; }
        }
        widx[tid] = bbi;
        dout[TOK_OFF + pb + tid] = (float)bbi;
    }
    __syncthreads();
    int idx = widx[p];
    float lsum = 0.0f;
    const float* cq = &cb[idx*EMB + g*8];
    const float* ze = &g_ze[(pb + p)*EMB + g*8];
    float*       zs = &g_zst[(pb + p)*EMB + g*8];
#pragma unroll
    for (int d = 0; d < 8; d++) {
        float zq = cq[d]; float z = ze[d];
        float diff = zq - z;
        zs[d] = z + diff;
        lsum = fmaf(diff, diff, lsum);
    }
    lred[tid] = lsum;
    __syncthreads();
    for (int s = 64; s > 0; s >>= 1) {
        if (tid < s) lred[tid] += lred[tid + s];
        __syncthreads();
    }
    if (tid == 0) atomicAdd(&g_loss, lred[0]);
}

// ================= convt1 (pipelined GEMM, f32x2): z_st -> g1 (gelu) =================
// block = 256 threads. tile: 128 ox (one row) x 128 co. grid (128 oy, 16 n). dyn smem.
// smem: ins [2kyi*8cik][67] = 1072 | Bs double buf 2 x 8192
__global__ void __launch_bounds__(256, 2) k_convt1(const float* __restrict__ w, const float* __restrict__ b) {
    extern __shared__ float sm[];
    float* ins = sm;            // 1072
    int tid = threadIdx.x;
    int oy = blockIdx.x, n = blockIdx.y;
    int pgx = tid & 15, cg = tid >> 4;
    int par = pgx >> 3, pa = pgx & 7;
    int co0 = cg * 8;
    int kyA = oy & 1;
    int iy0 = (oy + kyA - 2) >> 1;
    u64 acc2[8][4];
    {
        float4 b0 = *reinterpret_cast<const float4*>(&b[co0]);
        float4 b1 = *reinterpret_cast<const float4*>(&b[co0+4]);
        u64 p0 = pack2(b0.x,b0.y), p1 = pack2(b0.z,b0.w);
        u64 p2 = pack2(b1.x,b1.y), p3 = pack2(b1.z,b1.w);
#pragma unroll
        for (int j = 0; j < 8; j++) { acc2[j][0]=p0; acc2[j][1]=p1; acc2[j][2]=p2; acc2[j][3]=p3; }
    }
    int abase = 4*pa + par;

    float4 pin[2];
    auto ldg_ins = [&](int ch) {
        int ci0 = ch * 8;
#pragma unroll
        for (int u = 0; u < 2; u++) {
            int i = tid + u*256;
            if (i < 264) {
                int kyi = i / 132; int r = i - kyi*132; int ixl = r >> 1; int f4 = r & 1;
                int iy = iy0 + kyi; int ix = ixl - 1;
                float4 v = make_float4(0,0,0,0);
                if (iy >= 0 && iy < H2v && ix >= 0 && ix < W2v)
                    v = *reinterpret_cast<const float4*>(&g_zst[((n*H2v+iy)*W2v+ix)*EMB + ci0 + 4*f4]);
                pin[u] = v;
            }
        }
    };
    auto sts_ins = [&]() {
#pragma unroll
        for (int u = 0; u < 2; u++) {
            int i = tid + u*256;
            if (i < 264) {
                int kyi = i / 132; int r = i - kyi*132; int ixl = r >> 1; int f4 = r & 1;
                float* dst = &ins[(kyi*8 + 4*f4)*67 + ixl];
                float4 v = pin[u];
                dst[0] = v.x; dst[67] = v.y; dst[134] = v.z; dst[201] = v.w;
            }
        }
    };
    auto cp_bs = [&](int ch, float* Bbuf) {
        int ci0 = ch * 8;
#pragma unroll
        for (int u = 0; u < 8; u++) {
            int i = tid + u*256;    // float4 index [0, 2048)
            int co4 = i & 31; int cik = (i >> 5) & 7; int kx = (i >> 8) & 3; int kyi = i >> 10;
            int ky = kyA + 2*kyi;
            cp16(&Bbuf[((kyi*4+kx)*8+cik)*128 + co4*4],
                 &w[(((ky*4+kx)*EMB) + ci0 + cik)*HID + co4*4]);
        }
        CP_COMMIT();
    };

    cp_bs(0, sm + 1072);
    ldg_ins(0);
    sts_ins();
    CP_WAIT0();
    __syncthreads();
#pragma unroll 1
    for (int ch = 0; ch < 8; ch++) {
        float* Bs = sm + 1072 + (ch & 1) * 8192;
        if (ch < 7) {
            cp_bs(ch+1, sm + 1072 + ((ch+1) & 1) * 8192);
            ldg_ins(ch+1);
        }
#pragma unroll
        for (int cik = 0; cik < 8; cik++) {
#pragma unroll
            for (int kyi = 0; kyi < 2; kyi++) {
#pragma unroll
                for (int kxi = 0; kxi < 2; kxi++) {
                    int kx = par + 2*kxi;
                    const u64* bp = reinterpret_cast<const u64*>(&Bs[((kyi*4+kx)*8+cik)*128 + co0]);
                    u64 w01 = bp[0], w23 = bp[1], w45 = bp[2], w67 = bp[3];
                    const float* ap = &ins[(kyi*8+cik)*67 + abase + kxi];
                    float a0 = ap[0],  a1 = ap[1],  a2 = ap[2],  a3 = ap[3];
                    float a4 = ap[32], a5 = ap[33], a6 = ap[34], a7 = ap[35];
                    FFMA2_8(0,a0) FFMA2_8(1,a1) FFMA2_8(2,a2) FFMA2_8(3,a3)
                    FFMA2_8(4,a4) FFMA2_8(5,a5) FFMA2_8(6,a6) FFMA2_8(7,a7)
                }
            }
        }
        __syncthreads();
        if (ch < 7) {
            sts_ins();
            CP_WAIT0();
        }
        __syncthreads();
    }
#pragma unroll
    for (int j = 0; j < 8; j++) {
        int mxl = (j < 4) ? (4*pa + j) : (32 + 4*pa + j - 4);
        int ox = 2*mxl + par;
        float f0,f1,f2,f3,f4,f5,f6,f7;
        unpack2(acc2[j][0], f0, f1); unpack2(acc2[j][1], f2, f3);
        unpack2(acc2[j][2], f4, f5); unpack2(acc2[j][3], f6, f7);
        float4 o0 = make_float4(gelu_f(f0), gelu_f(f1), gelu_f(f2), gelu_f(f3));
        float4 o1 = make_float4(gelu_f(f4), gelu_f(f5), gelu_f(f6), gelu_f(f7));
        float* dst = &g_g1[((n*H1v+oy)*W1v + ox)*HID + co0];
        *reinterpret_cast<float4*>(dst)     = o0;
        *reinterpret_cast<float4*>(dst + 4) = o1;
    }
}

// ================= convt2 (pipelined GEMM, f32x2) + gelu + 1x1(128->3): g1 -> x_rec =================
// block = 256 threads. tile: 128 ox x 128 co. grid (2 bx, 256 oy, 16 n). dyn smem.
__global__ void __launch_bounds__(256, 2) k_convt2(const float* __restrict__ w, const float* __restrict__ b,
                                                   const float* __restrict__ w3, const float* __restrict__ b3,
                                                   float* __restrict__ dout) {
    extern __shared__ float sm[];
    float* ins = sm;            // 1072
    float* gs  = sm;            // reused in epilogue: [128 px][132] = 16896
    int tid = threadIdx.x;
    int bx = blockIdx.x, oy = blockIdx.y, n = blockIdx.z;
    int x0 = bx * 128, xb = bx * 64;
    int pgx = tid & 15, cg = tid >> 4;
    int par = pgx >> 3, pa = pgx & 7;
    int co0 = cg * 8;
    int kyA = oy & 1;
    int iy0 = (oy + kyA - 2) >> 1;
    u64 acc2[8][4];
    {
        float4 b0 = *reinterpret_cast<const float4*>(&b[co0]);
        float4 b1 = *reinterpret_cast<const float4*>(&b[co0+4]);
        u64 p0 = pack2(b0.x,b0.y), p1 = pack2(b0.z,b0.w);
        u64 p2 = pack2(b1.x,b1.y), p3 = pack2(b1.z,b1.w);
#pragma unroll
        for (int j = 0; j < 8; j++) { acc2[j][0]=p0; acc2[j][1]=p1; acc2[j][2]=p2; acc2[j][3]=p3; }
    }
    int abase = 4*pa + par;

    float4 pin[2];
    auto ldg_ins = [&](int ch) {
        int ci0 = ch * 8;
#pragma unroll
        for (int u = 0; u < 2; u++) {
            int i = tid + u*256;
            if (i < 264) {
                int kyi = i / 132; int r = i - kyi*132; int ixl = r >> 1; int f4 = r & 1;
                int iy = iy0 + kyi; int ix = xb + ixl - 1;
                float4 v = make_float4(0,0,0,0);
                if (iy >= 0 && iy < H1v && ix >= 0 && ix < W1v)
                    v = *reinterpret_cast<const float4*>(&g_g1[((n*H1v+iy)*W1v+ix)*HID + ci0 + 4*f4]);
                pin[u] = v;
            }
        }
    };
    auto sts_ins = [&]() {
#pragma unroll
        for (int u = 0; u < 2; u++) {
            int i = tid + u*256;
            if (i < 264) {
                int kyi = i / 132; int r = i - kyi*132; int ixl = r >> 1; int f4 = r & 1;
                float* dst = &ins[(kyi*8 + 4*f4)*67 + ixl];
                float4 v = pin[u];
                dst[0] = v.x; dst[67] = v.y; dst[134] = v.z; dst[201] = v.w;
            }
        }
    };
    auto cp_bs = [&](int ch, float* Bbuf) {
        int ci0 = ch * 8;
#pragma unroll
        for (int u = 0; u < 8; u++) {
            int i = tid + u*256;
            int co4 = i & 31; int cik = (i >> 5) & 7; int kx = (i >> 8) & 3; int kyi = i >> 10;
            int ky = kyA + 2*kyi;
            cp16(&Bbuf[((kyi*4+kx)*8+cik)*128 + co4*4],
                 &w[(((ky*4+kx)*HID) + ci0 + cik)*HID + co4*4]);
        }
        CP_COMMIT();
    };

    cp_bs(0, sm + 1072);
    ldg_ins(0);
    sts_ins();
    CP_WAIT0();
    __syncthreads();
#pragma unroll 1
    for (int ch = 0; ch < 16; ch++) {
        float* Bs = sm + 1072 + (ch & 1) * 8192;
        if (ch < 15) {
            cp_bs(ch+1, sm + 1072 + ((ch+1) & 1) * 8192);
            ldg_ins(ch+1);
        }
#pragma unroll
        for (int cik = 0; cik < 8; cik++) {
#pragma unroll
            for (int kyi = 0; kyi < 2; kyi++) {
#pragma unroll
                for (int kxi = 0; kxi < 2; kxi++) {
                    int kx = par + 2*kxi;
                    const u64* bp = reinterpret_cast<const u64*>(&Bs[((kyi*4+kx)*8+cik)*128 + co0]);
                    u64 w01 = bp[0], w23 = bp[1], w45 = bp[2], w67 = bp[3];
                    const float* ap = &ins[(kyi*8+cik)*67 + abase + kxi];
                    float a0 = ap[0],  a1 = ap[1],  a2 = ap[2],  a3 = ap[3];
                    float a4 = ap[32], a5 = ap[33], a6 = ap[34], a7 = ap[35];
                    FFMA2_8(0,a0) FFMA2_8(1,a1) FFMA2_8(2,a2) FFMA2_8(3,a3)
                    FFMA2_8(4,a4) FFMA2_8(5,a5) FFMA2_8(6,a6) FFMA2_8(7,a7)
                }
            }
        }
        __syncthreads();
        if (ch < 15) {
            sts_ins();
            CP_WAIT0();
        }
        __syncthreads();
    }
    // gelu -> gs [128 px][132]
#pragma unroll
    for (int j = 0; j < 8; j++) {
        int mxl = (j < 4) ? (4*pa + j) : (32 + 4*pa + j - 4);
        int ox = 2*mxl + par;
        float f0,f1,f2,f3,f4,f5,f6,f7;
        unpack2(acc2[j][0], f0, f1); unpack2(acc2[j][1], f2, f3);
        unpack2(acc2[j][2], f4, f5); unpack2(acc2[j][3], f6, f7);
        float4 o0 = make_float4(gelu_f(f0), gelu_f(f1), gelu_f(f2), gelu_f(f3));
        float4 o1 = make_float4(gelu_f(f4), gelu_f(f5), gelu_f(f6), gelu_f(f7));
        *reinterpret_cast<float4*>(&gs[ox*132 + co0])     = o0;
        *reinterpret_cast<float4*>(&gs[ox*132 + co0 + 4]) = o1;
    }
    __syncthreads();
    // fused 1x1: 128 -> 3. 2 threads per px, shfl combine.
    {
        int px = tid >> 1;
        int half = tid & 1;
        float p0 = 0.0f, p1 = 0.0f, p2 = 0.0f;
        const float* gp = &gs[px*132 + half*64];
        const float* wp = &w3[half*64*3];
#pragma unroll 8
        for (int k = 0; k < 64; k++) {
            float gv = gp[k];
            p0 = fmaf(gv, wp[3*k+0], p0);
            p1 = fmaf(gv, wp[3*k+1], p1);
            p2 = fmaf(gv, wp[3*k+2], p2);
        }
        p0 += __shfl_xor_sync(0xffffffffu, p0, 1);
        p1 += __shfl_xor_sync(0xffffffffu, p1, 1);
        p2 += __shfl_xor_sync(0xffffffffu, p2, 1);
        if (half == 0) {
            float* dst = &dout[((n*H0+oy)*W0 + x0 + px)*3];
            dst[0] = p0 + b3[0];
            dst[1] = p1 + b3[1];
            dst[2] = p2 + b3[2];
        }
    }
}

// ================= finalize losses =================
__global__ void k_final(float* __restrict__ dout) {
    float l = g_loss / (float)(TOK_ELEMS * EMB);
    dout[LOSS_OFF]     = l;
    dout[LOSS_OFF + 1] = l;
}

// ================= launch =================
extern "C" void kernel_launch(void* const* d_in, const int* in_sizes, int n_in,
                              void* d_out, int out_size) {
    const float* x      = (const float*)d_in[0];
    const float* enc_w1 = (const float*)d_in[1];
    const float* enc_b1 = (const float*)d_in[2];
    const float* enc_w2 = (const float*)d_in[3];
    const float* enc_b2 = (const float*)d_in[4];
    const float* enc_w3 = (const float*)d_in[5];
    const float* enc_b3 = (const float*)d_in[6];
    const float* cb     = (const float*)d_in[7];
    const float* dec_w1 = (const float*)d_in[8];
    const float* dec_b1 = (const float*)d_in[9];
    const float* dec_w2 = (const float*)d_in[10];
    const float* dec_b2 = (const float*)d_in[11];
    const float* dec_w3 = (const float*)d_in[12];
    const float* dec_b3 = (const float*)d_in[13];
    float* out = (float*)d_out;

    const int smem_c2 = (2112 + 2*8192) * 4;   // 73984 B
    const int smem_t1 = (1072 + 2*8192) * 4;   // 69824 B
    const int smem_t2 = (1072 + 2*8192) * 4;   // 69824 B (>= gs 16896*4)
    static int smem_set = 0;
    if (!smem_set) {
        cudaFuncSetAttribute(k_conv2,  cudaFuncAttributeMaxDynamicSharedMemorySize, smem_c2);
        cudaFuncSetAttribute(k_convt1, cudaFuncAttributeMaxDynamicSharedMemorySize, smem_t1);
        cudaFuncSetAttribute(k_convt2, cudaFuncAttributeMaxDynamicSharedMemorySize, smem_t2);
        smem_set = 1;
    }

    k_conv1<<<dim3(8, 128, 16), 128>>>(x, enc_w1, enc_b1);
    k_conv2<<<dim3(64, 16), 128, smem_c2>>>(enc_w2, enc_b2, enc_w3, enc_b3);
    k_vq<<<4096, 128>>>(cb, out);
    k_convt1<<<dim3(128, 16), 256, smem_t1>>>(dec_w1, dec_b1);
    k_convt2<<<dim3(2, 256, 16), 256, smem_t2>>>(dec_w2, dec_b2, dec_w3, dec_b3, out);
    k_final<<<1, 1>>>(out);
}

// round 8
// speedup vs baseline: 1.9601x; 1.9601x over previous
#include <cuda_runtime.h>
#include <math.h>
#include <mma.h>

using namespace nvcuda;

// ---------------- sizes ----------------
#define BATCH 16
#define H0 256
#define W0 256
#define CIN 3
#define HID 128
#define EMB 64
#define KCODES 1024
#define H1v 128
#define W1v 128
#define H2v 64
#define W2v 64

#define XREC_ELEMS (BATCH*H0*W0*3)      // 3145728
#define TOK_OFF    XREC_ELEMS
#define TOK_ELEMS  (BATCH*H2v*W2v)      // 65536
#define LOSS_OFF   (TOK_OFF + TOK_ELEMS)

typedef unsigned long long u64;

// ---------------- scratch ----------------
__device__ float g_h1[BATCH*H1v*W1v*HID];   // encoder conv1 out (gelu'd)
__device__ float g_ze[BATCH*H2v*W2v*EMB];   // z_e
__device__ float g_zst[BATCH*H2v*W2v*EMB];  // z_st
__device__ float g_g1[BATCH*H1v*W1v*HID];   // decoder convt1 out (gelu'd)
__device__ float g_loss;

__device__ __forceinline__ float gelu_f(float x) {
    float t = 0.7978845608028654f * (x + 0.044715f * x * x * x);
    return 0.5f * x * (1.0f + tanhf(t));
}

// ---------------- packed f32x2 helpers ----------------
__device__ __forceinline__ u64 splat2(float a) {
    u64 r; asm("mov.b64 %0, {%1, %1};" : "=l"(r) : "f"(a)); return r;
}
__device__ __forceinline__ u64 pack2(float lo, float hi) {
    u64 r; asm("mov.b64 %0, {%1, %2};" : "=l"(r) : "f"(lo), "f"(hi)); return r;
}
__device__ __forceinline__ void unpack2(u64 v, float& lo, float& hi) {
    asm("mov.b64 {%0, %1}, %2;" : "=f"(lo), "=f"(hi) : "l"(v));
}
__device__ __forceinline__ void ffma2(u64& d, u64 a, u64 b) {
    asm("fma.rn.f32x2 %0, %1, %2, %0;" : "+l"(d) : "l"(a), "l"(b));
}
#define FFMA2_8(J, AJ) { u64 s_ = splat2(AJ); \
    ffma2(acc2[J][0], s_, w01); ffma2(acc2[J][1], s_, w23); \
    ffma2(acc2[J][2], s_, w45); ffma2(acc2[J][3], s_, w67); }

// ================= conv1: x -> h1, 4x4 s2 SAME, gelu (fp32) =================
__global__ void k_conv1(const float* __restrict__ x, const float* __restrict__ w,
                        const float* __restrict__ b) {
    __shared__ float ws[4*4*3*128];
    __shared__ float ins[4*34*3];
    int tid = threadIdx.x;
    int bx = blockIdx.x, oy = blockIdx.y, n = blockIdx.z;
    if (bx == 0 && oy == 0 && n == 0 && tid == 0) g_loss = 0.0f;
    for (int i = tid; i < 6144; i += 128) ws[i] = w[i];
    int x0 = bx * 16;
    for (int i = tid; i < 4*34*3; i += 128) {
        int r = i / (34*3); int rem = i - r*(34*3); int c = rem / 3; int ch = rem % 3;
        int gy = 2*oy - 1 + r;
        int gx = 2*x0 - 1 + c;
        float v = 0.0f;
        if (gy >= 0 && gy < H0 && gx >= 0 && gx < W0) v = x[((n*H0+gy)*W0+gx)*CIN + ch];
        ins[i] = v;
    }
    __syncthreads();
    int co = tid;
    float bias = b[co];
    u64 acc2[8];
#pragma unroll
    for (int pp = 0; pp < 8; pp++) acc2[pp] = pack2(bias, bias);
    for (int ky = 0; ky < 4; ky++) {
        for (int kx = 0; kx < 4; kx++) {
#pragma unroll
            for (int ci = 0; ci < 3; ci++) {
                float wv = ws[((ky*4+kx)*3+ci)*128 + co];
                u64 wvv = splat2(wv);
#pragma unroll
                for (int pp = 0; pp < 8; pp++) {
                    u64 av = pack2(ins[(ky*34 + 4*pp + kx)*3 + ci],
                                   ins[(ky*34 + 4*pp + 2 + kx)*3 + ci]);
                    ffma2(acc2[pp], av, wvv);
                }
            }
        }
    }
#pragma unroll
    for (int pp = 0; pp < 8; pp++) {
        float v0, v1; unpack2(acc2[pp], v0, v1);
        g_h1[((n*H1v+oy)*W1v + x0 + 2*pp)*HID + co]     = gelu_f(v0);
        g_h1[((n*H1v+oy)*W1v + x0 + 2*pp + 1)*HID + co] = gelu_f(v1);
    }
}

// ================= conv2 (R5 GEMM-tiled, f32x2) + gelu + 1x1: h1 -> z_e =================
__global__ void __launch_bounds__(128) k_conv2(const float* __restrict__ w2, const float* __restrict__ b2,
                                               const float* __restrict__ w3, const float* __restrict__ b3) {
    __shared__ float sm[2112 + 8192];
    float* ins = sm;
    float* Bs  = sm + 2112;
    float* h2s = sm;
    int tid = threadIdx.x;
    int oy = blockIdx.x, n = blockIdx.y;
    int pa = tid & 7, cg = tid >> 3;
    int co0 = cg * 8;
    u64 acc2[8][4];
    {
        float4 b0 = *reinterpret_cast<const float4*>(&b2[co0]);
        float4 b1 = *reinterpret_cast<const float4*>(&b2[co0+4]);
        u64 p0 = pack2(b0.x,b0.y), p1 = pack2(b0.z,b0.w);
        u64 p2 = pack2(b1.x,b1.y), p3 = pack2(b1.z,b1.w);
#pragma unroll
        for (int j = 0; j < 8; j++) { acc2[j][0]=p0; acc2[j][1]=p1; acc2[j][2]=p2; acc2[j][3]=p3; }
    }
    int axbase = 2 * pa;
#pragma unroll 1
    for (int ch = 0; ch < 32; ch++) {
        int ci0 = ch * 4;
        for (int i = tid; i < 520; i += 128) {
            int r = i / 130; int ixl = i - r*130;
            int iy = 2*oy - 1 + r;
            int ix = ixl - 1;
            float4 v = make_float4(0,0,0,0);
            if (iy >= 0 && iy < H1v && ix >= 0 && ix < W1v)
                v = *reinterpret_cast<const float4*>(&g_h1[((n*H1v+iy)*W1v+ix)*HID + ci0]);
            float* dst = &ins[(r*4)*132 + ixl];
            dst[0] = v.x; dst[132] = v.y; dst[264] = v.z; dst[396] = v.w;
        }
        for (int i = tid; i < 2048; i += 128) {
            int co4 = i & 31; int cik = (i >> 5) & 3; int tap = i >> 7;
            float4 wv = *reinterpret_cast<const float4*>(&w2[((tap*HID) + ci0 + cik)*HID + co4*4]);
            *reinterpret_cast<float4*>(&Bs[(tap*4+cik)*128 + co4*4]) = wv;
        }
        __syncthreads();
        for (int tap = 0; tap < 16; tap++) {
            int kx = tap & 3; int row = tap >> 2;
#pragma unroll
            for (int cik = 0; cik < 4; cik++) {
                const u64* bp = reinterpret_cast<const u64*>(&Bs[(tap*4+cik)*128 + co0]);
                u64 w01 = bp[0], w23 = bp[1], w45 = bp[2], w67 = bp[3];
                const float* ap = &ins[(row*4+cik)*132 + axbase + kx];
                float a0 = ap[0],  a1 = ap[16], a2 = ap[32], a3 = ap[48];
                float a4 = ap[64], a5 = ap[80], a6 = ap[96], a7 = ap[112];
                FFMA2_8(0,a0) FFMA2_8(1,a1) FFMA2_8(2,a2) FFMA2_8(3,a3)
                FFMA2_8(4,a4) FFMA2_8(5,a5) FFMA2_8(6,a6) FFMA2_8(7,a7)
            }
        }
        __syncthreads();
    }
#pragma unroll
    for (int j = 0; j < 8; j++) {
        int ox = pa + 8*j;
        float f0,f1,f2,f3,f4,f5,f6,f7;
        unpack2(acc2[j][0], f0, f1); unpack2(acc2[j][1], f2, f3);
        unpack2(acc2[j][2], f4, f5); unpack2(acc2[j][3], f6, f7);
        float4 o0 = make_float4(gelu_f(f0), gelu_f(f1), gelu_f(f2), gelu_f(f3));
        float4 o1 = make_float4(gelu_f(f4), gelu_f(f5), gelu_f(f6), gelu_f(f7));
        *reinterpret_cast<float4*>(&h2s[ox*132 + co0])     = o0;
        *reinterpret_cast<float4*>(&h2s[ox*132 + co0 + 4]) = o1;
    }
    __syncthreads();
    {
        int px = tid >> 1;
        int e0 = (tid & 1) * 32;
        u64 z2[16];
#pragma unroll
        for (int u = 0; u < 8; u++) {
            float4 bb = *reinterpret_cast<const float4*>(&b3[e0 + 4*u]);
            z2[2*u]   = pack2(bb.x, bb.y);
            z2[2*u+1] = pack2(bb.z, bb.w);
        }
#pragma unroll 4
        for (int ci = 0; ci < 128; ci++) {
            float hv = h2s[px*132 + ci];
            u64 s = splat2(hv);
#pragma unroll
            for (int u = 0; u < 8; u++) {
                float4 wv = *reinterpret_cast<const float4*>(&w3[ci*EMB + e0 + 4*u]);
                ffma2(z2[2*u],   s, pack2(wv.x, wv.y));
                ffma2(z2[2*u+1], s, pack2(wv.z, wv.w));
            }
        }
        float* dst = &g_ze[((n*H2v+oy)*W2v + px)*EMB + e0];
#pragma unroll
        for (int u = 0; u < 8; u++) {
            float f0,f1,f2,f3;
            unpack2(z2[2*u], f0, f1); unpack2(z2[2*u+1], f2, f3);
            *reinterpret_cast<float4*>(dst + 4*u) = make_float4(f0, f1, f2, f3);
        }
    }
}

// ================= VQ =================
#define CSTR 68
__global__ void k_vq(const float* __restrict__ cb, float* __restrict__ dout) {
    __shared__ float cs[64*CSTR];
    __shared__ float e2s[64];
    __shared__ float bval[128];
    __shared__ int   bidx[128];
    __shared__ int   widx[16];
    __shared__ float lred[128];
    int tid = threadIdx.x;
    int pb = blockIdx.x * 16;
    int p = tid & 15;
    int g = tid >> 4;
    float4 z4[16];
    const float* zp = &g_ze[(pb + p)*EMB];
#pragma unroll
    for (int i = 0; i < 16; i++) z4[i] = *reinterpret_cast<const float4*>(&zp[4*i]);
    float best = 3.4e38f; int bi = 0;
    for (int ch = 0; ch < 16; ch++) {
        for (int i = tid; i < 64*16; i += 128) {
            int cj = i >> 4; int d4 = i & 15;
            float4 v = *reinterpret_cast<const float4*>(&cb[(ch*64+cj)*EMB + 4*d4]);
            *reinterpret_cast<float4*>(&cs[cj*CSTR + 4*d4]) = v;
        }
        __syncthreads();
        if (tid < 64) {
            float s = 0.0f;
#pragma unroll 8
            for (int d = 0; d < 64; d++) { float c = cs[tid*CSTR + d]; s = fmaf(c, c, s); }
            e2s[tid] = s;
        }
        __syncthreads();
#pragma unroll
        for (int j = 0; j < 8; j++) {
            int cj = g*8 + j;
            const float* cp = &cs[cj*CSTR];
            float dot = 0.0f;
#pragma unroll
            for (int i = 0; i < 16; i++) {
                float4 c = *reinterpret_cast<const float4*>(&cp[4*i]);
                dot = fmaf(z4[i].x, c.x, dot); dot = fmaf(z4[i].y, c.y, dot);
                dot = fmaf(z4[i].z, c.z, dot); dot = fmaf(z4[i].w, c.w, dot);
            }
            float dist = e2s[cj] - 2.0f*dot;
            int gidx = ch*64 + cj;
            if (dist < best || (dist == best && gidx < bi)) { best = dist; bi = gidx; }
        }
        __syncthreads();
    }
    bval[tid] = best; bidx[tid] = bi;
    __syncthreads();
    if (tid < 16) {
        float bb = bval[tid]; int bbi = bidx[tid];
        for (int k = 1; k < 8; k++) {
            float v = bval[tid + 16*k]; int vi = bidx[tid + 16*k];
            if (v < bb || (v == bb && vi < bbi)) { bb = v; bbi = vi; }
        }
        widx[tid] = bbi;
        dout[TOK_OFF + pb + tid] = (float)bbi;
    }
    __syncthreads();
    int idx = widx[p];
    float lsum = 0.0f;
    const float* cq = &cb[idx*EMB + g*8];
    const float* ze = &g_ze[(pb + p)*EMB + g*8];
    float*       zs = &g_zst[(pb + p)*EMB + g*8];
#pragma unroll
    for (int d = 0; d < 8; d++) {
        float zq = cq[d]; float z = ze[d];
        float diff = zq - z;
        zs[d] = z + diff;
        lsum = fmaf(diff, diff, lsum);
    }
    lred[tid] = lsum;
    __syncthreads();
    for (int s = 64; s > 0; s >>= 1) {
        if (tid < s) lred[tid] += lred[tid + s];
        __syncthreads();
    }
    if (tid == 0) atomicAdd(&g_loss, lred[0]);
}

// ================= WMMA tf32 transposed-conv =================
// CTA: one parity tile. M=128 (2 output rows x 64 same-parity px), N=128 co,
// K = 2kyi*2kxi*CI in chunks of 32. 256 threads = 8 warps (4 m x 2 n).
// A: [128 m][32 k] stride 36. B: [32 k][128 co] stride 132 (w is already K x N).
// Epilogue: accum -> smem Cs [128][132] -> bias+gelu (+1x1 RGB).
#define AST 36
#define BST 132
template<int CI, int HIN, int WIN, bool RGB>
__global__ void __launch_bounds__(256, 2) k_convt_wmma(
    const float* __restrict__ src, const float* __restrict__ w,
    const float* __restrict__ bias,
    const float* __restrict__ w3, const float* __restrict__ b3,
    float* __restrict__ dst)
{
    constexpr int CIC  = CI / 32;
    constexpr int NCH  = 4 * CIC;
    constexpr int HOUT = 2 * HIN;
    constexpr int WOUT = 2 * WIN;

    extern __shared__ float smf[];
    float* As    = smf;             // 128*36 = 4608
    float* Bs    = smf + 4608;      // 32*132 = 4224
    float* Cs    = smf;             // epilogue reuse: 128*132 = 16896
    float* biass = smf + 16896;     // 128
    float* w3s   = smf + 17024;     // 384
    float* b3s   = smf + 17408;     // 3

    int tid = threadIdx.x;
    int bx = blockIdx.x, pr = blockIdx.y, n = blockIdx.z;
    int t  = bx & 1;
    int xh = bx >> 1;
    int oy = 4*(pr >> 1) + (pr & 1);          // rows oy, oy+2
    int x0 = xh * 128;
    int xhalf = x0 >> 1;
    int kyA = oy & 1;
    int iy0 = (oy + kyA - 2) >> 1;

    for (int i = tid; i < 128; i += 256) biass[i] = bias[i];
    if (RGB) {
        for (int i = tid; i < 384; i += 256) w3s[i] = w3[i];
        if (tid < 3) b3s[tid] = b3[tid];
    }

    int wid = tid >> 5;
    int m0 = (wid & 3) * 32;
    int n0 = (wid >> 2) * 64;

    wmma::fragment<wmma::accumulator, 16, 16, 8, float> acc[2][4];
#pragma unroll
    for (int im = 0; im < 2; im++)
#pragma unroll
        for (int in = 0; in < 4; in++) wmma::fill_fragment(acc[im][in], 0.0f);

#pragma unroll 1
    for (int c = 0; c < NCH; c++) {
        int kyi = c / (2*CIC);
        int kxi = (c / CIC) & 1;
        int ci0 = (c % CIC) * 32;
        __syncthreads();
        // stage A: 128 rows x 32 floats (1024 float4)
        {
            int xb = xhalf + t + kxi - 1;
#pragma unroll
            for (int q = 0; q < 4; q++) {
                int u = tid + q*256;
                int m = u >> 3, c8 = u & 7;
                int h = m >> 6, j = m & 63;
                int y = iy0 + h + kyi;
                int col = xb + j;
                float4 v = make_float4(0,0,0,0);
                if (y >= 0 && y < HIN && col >= 0 && col < WIN)
                    v = *reinterpret_cast<const float4*>(
                        &src[((size_t)((n*HIN + y)*WIN + col))*CI + ci0 + 4*c8]);
                *reinterpret_cast<float4*>(&As[m*AST + 4*c8]) = v;
            }
        }
        // stage B: 32 rows x 128 floats (1024 float4); w row-major [K][128]
        {
            int k0 = ((kyA + 2*kyi)*4 + (t + 2*kxi))*CI + ci0;
#pragma unroll
            for (int q = 0; q < 4; q++) {
                int u = tid + q*256;
                int kk = u >> 5, c32 = u & 31;
                float4 v = *reinterpret_cast<const float4*>(&w[(size_t)(k0 + kk)*128 + 4*c32]);
                *reinterpret_cast<float4*>(&Bs[kk*BST + 4*c32]) = v;
            }
        }
        __syncthreads();
#pragma unroll
        for (int ks = 0; ks < 4; ks++) {
            int kk = ks * 8;
            wmma::fragment<wmma::matrix_a, 16, 16, 8, wmma::precision::tf32, wmma::row_major> af[2];
            wmma::fragment<wmma::matrix_b, 16, 16, 8, wmma::precision::tf32, wmma::row_major> bf[4];
#pragma unroll
            for (int im = 0; im < 2; im++) {
                wmma::load_matrix_sync(af[im], &As[(m0 + 16*im)*AST + kk], AST);
#pragma unroll
                for (int e = 0; e < af[im].num_elements; e++)
                    af[im].x[e] = wmma::__float_to_tf32(af[im].x[e]);
            }
#pragma unroll
            for (int in = 0; in < 4; in++) {
                wmma::load_matrix_sync(bf[in], &Bs[kk*BST + n0 + 16*in], BST);
#pragma unroll
                for (int e = 0; e < bf[in].num_elements; e++)
                    bf[in].x[e] = wmma::__float_to_tf32(bf[in].x[e]);
            }
#pragma unroll
            for (int im = 0; im < 2; im++)
#pragma unroll
                for (int in = 0; in < 4; in++)
                    wmma::mma_sync(acc[im][in], af[im], bf[in], acc[im][in]);
        }
    }
    __syncthreads();
    // store accumulators to Cs
#pragma unroll
    for (int im = 0; im < 2; im++)
#pragma unroll
        for (int in = 0; in < 4; in++)
            wmma::store_matrix_sync(&Cs[(m0 + 16*im)*BST + n0 + 16*in],
                                    acc[im][in], BST, wmma::mem_row_major);
    __syncthreads();
    // epilogue
    {
        int m = tid >> 1;
        int half = tid & 1;
        int h = m >> 6, j = m & 63;
        int row = oy + 2*h;
        int ox = x0 + 2*j + t;
        const float* cp = &Cs[m*BST + half*64];
        if (RGB) {
            float r = 0.0f, g = 0.0f, bl = 0.0f;
#pragma unroll 8
            for (int kk = 0; kk < 64; kk++) {
                int cc = half*64 + kk;
                float gv = gelu_f(cp[kk] + biass[cc]);
                r  = fmaf(gv, w3s[cc*3+0], r);
                g  = fmaf(gv, w3s[cc*3+1], g);
                bl = fmaf(gv, w3s[cc*3+2], bl);
            }
            r  += __shfl_xor_sync(0xffffffffu, r, 1);
            g  += __shfl_xor_sync(0xffffffffu, g, 1);
            bl += __shfl_xor_sync(0xffffffffu, bl, 1);
            if (half == 0) {
                float* dp = dst + ((size_t)((n*HOUT + row)*WOUT + ox))*3;
                dp[0] = r + b3s[0];
                dp[1] = g + b3s[1];
                dp[2] = bl + b3s[2];
            }
        } else {
            float* dp = dst + ((size_t)((n*HOUT + row)*WOUT + ox))*128 + half*64;
#pragma unroll
            for (int k4 = 0; k4 < 16; k4++) {
                float4 o;
                o.x = gelu_f(cp[4*k4+0] + biass[half*64 + 4*k4+0]);
                o.y = gelu_f(cp[4*k4+1] + biass[half*64 + 4*k4+1]);
                o.z = gelu_f(cp[4*k4+2] + biass[half*64 + 4*k4+2]);
                o.w = gelu_f(cp[4*k4+3] + biass[half*64 + 4*k4+3]);
                *reinterpret_cast<float4*>(dp + 4*k4) = o;
            }
        }
    }
}

// ================= finalize losses =================
__global__ void k_final(float* __restrict__ dout) {
    float l = g_loss / (float)(TOK_ELEMS * EMB);
    dout[LOSS_OFF]     = l;
    dout[LOSS_OFF + 1] = l;
}

// ================= launch =================
extern "C" void kernel_launch(void* const* d_in, const int* in_sizes, int n_in,
                              void* d_out, int out_size) {
    const float* x      = (const float*)d_in[0];
    const float* enc_w1 = (const float*)d_in[1];
    const float* enc_b1 = (const float*)d_in[2];
    const float* enc_w2 = (const float*)d_in[3];
    const float* enc_b2 = (const float*)d_in[4];
    const float* enc_w3 = (const float*)d_in[5];
    const float* enc_b3 = (const float*)d_in[6];
    const float* cb     = (const float*)d_in[7];
    const float* dec_w1 = (const float*)d_in[8];
    const float* dec_b1 = (const float*)d_in[9];
    const float* dec_w2 = (const float*)d_in[10];
    const float* dec_b2 = (const float*)d_in[11];
    const float* dec_w3 = (const float*)d_in[12];
    const float* dec_b3 = (const float*)d_in[13];
    float* out = (float*)d_out;

    const int smem_w = 17412 * 4;   // 69648 B
    static int smem_set = 0;
    if (!smem_set) {
        cudaFuncSetAttribute(k_convt_wmma<64, 64, 64, false>,
                             cudaFuncAttributeMaxDynamicSharedMemorySize, smem_w);
        cudaFuncSetAttribute(k_convt_wmma<128, 128, 128, true>,
                             cudaFuncAttributeMaxDynamicSharedMemorySize, smem_w);
        smem_set = 1;
    }

    k_conv1<<<dim3(8, 128, 16), 128>>>(x, enc_w1, enc_b1);
    k_conv2<<<dim3(64, 16), 128>>>(enc_w2, enc_b2, enc_w3, enc_b3);
    k_vq<<<4096, 128>>>(cb, out);

    float* zstp; cudaGetSymbolAddress((void**)&zstp, g_zst);
    float* g1p;  cudaGetSymbolAddress((void**)&g1p, g_g1);

    k_convt_wmma<64, 64, 64, false><<<dim3(2, 64, 16), 256, smem_w>>>(
        zstp, dec_w1, dec_b1, nullptr, nullptr, g1p);
    k_convt_wmma<128, 128, 128, true><<<dim3(4, 128, 16), 256, smem_w>>>(
        g1p, dec_w2, dec_b2, dec_w3, dec_b3, out);
    k_final<<<1, 1>>>(out);
}